// round 6
// baseline (speedup 1.0000x reference)
#include <cuda_runtime.h>
#include <stdint.h>

#define BB 1024
#define DD 512
#define HH 512
#define AA 18
#define TT 64

// scratch (device globals: no allocation allowed)
__device__ int   g_sorted[BB];
__device__ int   g_start[TT + 1];
__device__ float g_h[BB * HH];   // hidden activations, task-sorted order

// ---------------------------------------------------------------------------
// threefry2x32 (JAX reference rotations, 20 rounds)
// ---------------------------------------------------------------------------
__device__ __forceinline__ uint32_t rotl32(uint32_t x, int r) {
    return (x << r) | (x >> (32 - r));
}

__device__ __forceinline__ uint2 threefry2x32(uint32_t k0, uint32_t k1,
                                              uint32_t x0, uint32_t x1) {
    uint32_t k2 = k0 ^ k1 ^ 0x1BD11BDAu;
    x0 += k0; x1 += k1;
#define TF_RND(r) { x0 += x1; x1 = rotl32(x1, r); x1 ^= x0; }
    TF_RND(13) TF_RND(15) TF_RND(26) TF_RND(6)
    x0 += k1; x1 += k2 + 1u;
    TF_RND(17) TF_RND(29) TF_RND(16) TF_RND(24)
    x0 += k2; x1 += k0 + 2u;
    TF_RND(13) TF_RND(15) TF_RND(26) TF_RND(6)
    x0 += k0; x1 += k1 + 3u;
    TF_RND(17) TF_RND(29) TF_RND(16) TF_RND(24)
    x0 += k1; x1 += k2 + 4u;
    TF_RND(13) TF_RND(15) TF_RND(26) TF_RND(6)
    x0 += k2; x1 += k0 + 5u;
#undef TF_RND
    return make_uint2(x0, x1);
}

// JAX >= 0.5 default: threefry_partitionable = True.
// 32-bit random bits for flat index i (counts = iota(uint64), so for
// i < 2^32: x0 = hi32(i) = 0, x1 = lo32(i) = i), output = y0 ^ y1.
// key = jax.random.key(1) -> (0, 1).
__device__ __forceinline__ uint32_t jax_bits(int i) {
    uint2 r = threefry2x32(0u, 1u, 0u, (uint32_t)i);
    return r.x ^ r.y;
}

// ---------------------------------------------------------------------------
// Kernel 1: detect task_id dtype (int32 vs int64) and group samples by task.
// int64 layout: odd 32-bit words (high halves of values < 64) are all zero.
// ---------------------------------------------------------------------------
__global__ void group_kernel(const void* __restrict__ task_ptr) {
    __shared__ int counts[TT];
    __shared__ int offs[TT + 1];
    __shared__ int odd_or;
    int t = threadIdx.x;
    if (t == 0) odd_or = 0;
    if (t < TT) counts[t] = 0;
    __syncthreads();

    const int* w = (const int*)task_ptr;
    if (t < BB / 2) {
        if (w[2 * t + 1] != 0) atomicOr(&odd_or, 1);
    }
    __syncthreads();
    bool is64 = (odd_or == 0);
    int task = is64 ? w[2 * t] : w[t];
    task &= (TT - 1);   // safety clamp (no-op for valid data)
    atomicAdd(&counts[task], 1);
    __syncthreads();
    if (t == 0) {
        int s = 0;
        for (int i = 0; i < TT; i++) { offs[i] = s; s += counts[i]; }
        offs[TT] = s;
    }
    __syncthreads();
    if (t <= TT) g_start[t] = offs[t];
    if (t < TT) counts[t] = offs[t];   // reuse as cursor
    __syncthreads();
    int pos = atomicAdd(&counts[task], 1);
    g_sorted[pos] = t;
}

// ---------------------------------------------------------------------------
// Kernel 2: fc1 per-task GEMM  h = relu(x * W1[t] + b1[t])
// grid (H/128, T), block 128 threads. Tile: M=16, N=128, K-step 32.
// Each thread: 4x4 register tile.
// ---------------------------------------------------------------------------
__global__ void __launch_bounds__(128)
fc1_kernel(const float* __restrict__ xs, const float* __restrict__ w1,
           const float* __restrict__ b1) {
    int task = blockIdx.y;
    int n0 = blockIdx.x * 128;
    int start = g_start[task], end = g_start[task + 1];
    if (start == end) return;

    __shared__ float Xs[32][16];
    __shared__ float Ws[32][128];
    __shared__ float bias[128];

    int tid = threadIdx.x;
    int tm = tid & 3;
    int tn = tid >> 2;
    const float* w1t = w1 + (size_t)task * DD * HH;
    bias[tid] = b1[task * HH + n0 + tid];

    for (int m0 = start; m0 < end; m0 += 16) {
        float acc[4][4];
#pragma unroll
        for (int i = 0; i < 4; i++)
#pragma unroll
            for (int j = 0; j < 4; j++) acc[i][j] = 0.f;

        for (int k0 = 0; k0 < DD; k0 += 32) {
            // X tile: 512 elems / 128 thr = 4 each (m fastest -> conflict-free STS)
#pragma unroll
            for (int i = 0; i < 4; i++) {
                int idx = tid + i * 128;
                int kk = idx >> 4, m = idx & 15;
                int gm = m0 + m;
                float v = 0.f;
                if (gm < end) v = xs[(size_t)g_sorted[gm] * DD + k0 + kk];
                Xs[kk][m] = v;
            }
            // W tile: 4096 elems = 8 float4 each, coalesced rows
#pragma unroll
            for (int i = 0; i < 8; i++) {
                int idx = (tid + i * 128) * 4;
                int kk = idx >> 7, n = idx & 127;
                float4 v = *(const float4*)(w1t + (size_t)(k0 + kk) * HH + n0 + n);
                *(float4*)&Ws[kk][n] = v;
            }
            __syncthreads();
#pragma unroll
            for (int kk = 0; kk < 32; kk++) {
                float4 xv = *(float4*)&Xs[kk][tm * 4];
                float4 wv = *(float4*)&Ws[kk][tn * 4];
                float xr[4] = {xv.x, xv.y, xv.z, xv.w};
                float wr[4] = {wv.x, wv.y, wv.z, wv.w};
#pragma unroll
                for (int i = 0; i < 4; i++)
#pragma unroll
                    for (int j = 0; j < 4; j++) acc[i][j] += xr[i] * wr[j];
            }
            __syncthreads();
        }
        // epilogue: bias + relu, store sorted-order hidden rows
#pragma unroll
        for (int i = 0; i < 4; i++) {
            int gm = m0 + tm * 4 + i;
            if (gm < end) {
                float4 o;
                o.x = fmaxf(acc[i][0] + bias[tn * 4 + 0], 0.f);
                o.y = fmaxf(acc[i][1] + bias[tn * 4 + 1], 0.f);
                o.z = fmaxf(acc[i][2] + bias[tn * 4 + 2], 0.f);
                o.w = fmaxf(acc[i][3] + bias[tn * 4 + 3], 0.f);
                *(float4*)&g_h[(size_t)gm * HH + n0 + tn * 4] = o;
            }
        }
        __syncthreads();
    }
}

// ---------------------------------------------------------------------------
// Kernel 3: fc2 + log_softmax + categorical sampling + log_prob + entropy
// grid T, block 256 (8 warps). W2[t] staged in smem (pad 19). Warp per sample.
// ---------------------------------------------------------------------------
__global__ void __launch_bounds__(256)
fc2_kernel(const float* __restrict__ w2, const float* __restrict__ b2,
           float* __restrict__ out, int out_mode) {
    int task = blockIdx.x;
    __shared__ float Ws[DD * 19];
    __shared__ float b2s[AA];
    int tid = threadIdx.x;

    const float* w2t = w2 + (size_t)task * DD * AA;
    for (int i = tid; i < DD * AA; i += 256) {
        int k = i / AA, a = i % AA;
        Ws[k * 19 + a] = w2t[i];
    }
    if (tid < AA) b2s[tid] = b2[task * AA + tid];
    __syncthreads();

    int start = g_start[task], end = g_start[task + 1];
    int warp = tid >> 5, lane = tid & 31;

    for (int m = start + warp; m < end; m += 8) {
        const float* hrow = g_h + (size_t)m * HH;
        float acc[AA];
#pragma unroll
        for (int a = 0; a < AA; a++) acc[a] = 0.f;

        for (int k = lane; k < HH; k += 32) {
            float hv = hrow[k];
            const float* wr = &Ws[k * 19];
#pragma unroll
            for (int a = 0; a < AA; a++) acc[a] += hv * wr[a];
        }
#pragma unroll
        for (int off = 16; off; off >>= 1)
#pragma unroll
            for (int a = 0; a < AA; a++)
                acc[a] += __shfl_xor_sync(0xFFFFFFFFu, acc[a], off);

        int b = g_sorted[m];
        float logit = (lane < AA) ? acc[lane] + b2s[lane] : -INFINITY;

        // log_softmax
        float mx = logit;
#pragma unroll
        for (int off = 16; off; off >>= 1)
            mx = fmaxf(mx, __shfl_xor_sync(0xFFFFFFFFu, mx, off));
        float ex = (lane < AA) ? expf(logit - mx) : 0.f;
        float s = ex;
#pragma unroll
        for (int off = 16; off; off >>= 1)
            s += __shfl_xor_sync(0xFFFFFFFFu, s, off);
        float lse = logf(s);
        float logp = logit - mx - lse;

        // JAX gumbel noise for flat index (b*18 + lane), partitionable stream
        float v = -INFINITY;
        if (lane < AA) {
            uint32_t bits = jax_bits(b * AA + lane);
            float f = __uint_as_float((bits >> 9) | 0x3f800000u) - 1.0f;
            const float tiny = 1.1754943508222875e-38f;
            float u = fmaxf(tiny, f + tiny);
            float g = -logf(-logf(u));
            v = logit + g;
        }
        // argmax, first-index tie-break
        float bv = v;
        int bi = (lane < AA) ? lane : 31;
#pragma unroll
        for (int off = 16; off; off >>= 1) {
            float ov = __shfl_xor_sync(0xFFFFFFFFu, bv, off);
            int oi = __shfl_xor_sync(0xFFFFFFFFu, bi, off);
            if (ov > bv || (ov == bv && oi < bi)) { bv = ov; bi = oi; }
        }
        int action = bi;
        float lp_sel = __shfl_sync(0xFFFFFFFFu, logp, action);

        float term = (lane < AA) ? -(ex / s) * logp : 0.f;
        float ent = term;
#pragma unroll
        for (int off = 16; off; off >>= 1)
            ent += __shfl_xor_sync(0xFFFFFFFFu, ent, off);

        if (lane == 0) {
            if (out_mode == 0) {
                out[b]          = (float)action;
                out[BB + b]     = lp_sel;
                out[2 * BB + b] = ent;
            } else {
                ((long long*)out)[b] = (long long)action;
                out[2 * BB + b]      = lp_sel;
                out[3 * BB + b]      = ent;
            }
        }
    }
}

// ---------------------------------------------------------------------------
extern "C" void kernel_launch(void* const* d_in, const int* in_sizes, int n_in,
                              void* d_out, int out_size) {
    // Bind inputs by element count (all six distinct) -- order-proof.
    const float* xs = nullptr; const void* task_id = nullptr;
    const float* w1 = nullptr; const float* b1 = nullptr;
    const float* w2 = nullptr; const float* b2 = nullptr;
    for (int i = 0; i < n_in; i++) {
        switch (in_sizes[i]) {
            case BB * DD:       xs      = (const float*)d_in[i]; break;  // 524288
            case BB:            task_id = d_in[i];               break;  // 1024
            case TT * DD * HH:  w1      = (const float*)d_in[i]; break;  // 16777216
            case TT * HH:       b1      = (const float*)d_in[i]; break;  // 32768
            case TT * HH * AA:  w2      = (const float*)d_in[i]; break;  // 589824
            case TT * AA:       b2      = (const float*)d_in[i]; break;  // 1152
            default: break;
        }
    }
    float* out = (float*)d_out;
    int out_mode = (out_size == 4 * BB) ? 1 : 0;  // 4096 => int64 action + f32 pair

    group_kernel<<<1, BB>>>(task_id);
    dim3 g1(HH / 128, TT);
    fc1_kernel<<<g1, 128>>>(xs, w1, b1);
    fc2_kernel<<<TT, 256>>>(w2, b2, out, out_mode);
}

// round 9
// speedup vs baseline: 1.3192x; 1.3192x over previous
#include <cuda_runtime.h>
#include <stdint.h>

#define BB 1024
#define DD 512
#define HH 512
#define AA 18
#define TT 64

// scratch (device globals: no allocation allowed)
__device__ int   g_sorted[BB];
__device__ int   g_start[TT + 1];
__device__ float g_h[BB * HH];   // hidden activations, task-sorted order

// ---------------------------------------------------------------------------
// threefry2x32 (JAX reference rotations, 20 rounds)
// ---------------------------------------------------------------------------
__device__ __forceinline__ uint32_t rotl32(uint32_t x, int r) {
    return (x << r) | (x >> (32 - r));
}

__device__ __forceinline__ uint2 threefry2x32(uint32_t k0, uint32_t k1,
                                              uint32_t x0, uint32_t x1) {
    uint32_t k2 = k0 ^ k1 ^ 0x1BD11BDAu;
    x0 += k0; x1 += k1;
#define TF_RND(r) { x0 += x1; x1 = rotl32(x1, r); x1 ^= x0; }
    TF_RND(13) TF_RND(15) TF_RND(26) TF_RND(6)
    x0 += k1; x1 += k2 + 1u;
    TF_RND(17) TF_RND(29) TF_RND(16) TF_RND(24)
    x0 += k2; x1 += k0 + 2u;
    TF_RND(13) TF_RND(15) TF_RND(26) TF_RND(6)
    x0 += k0; x1 += k1 + 3u;
    TF_RND(17) TF_RND(29) TF_RND(16) TF_RND(24)
    x0 += k1; x1 += k2 + 4u;
    TF_RND(13) TF_RND(15) TF_RND(26) TF_RND(6)
    x0 += k2; x1 += k0 + 5u;
#undef TF_RND
    return make_uint2(x0, x1);
}

// JAX >= 0.5 default: threefry_partitionable = True.
// bits[i] = y0 ^ y1 of threefry(key=(0,1), x=(hi32(i)=0, lo32(i)=i)).
__device__ __forceinline__ uint32_t jax_bits(int i) {
    uint2 r = threefry2x32(0u, 1u, 0u, (uint32_t)i);
    return r.x ^ r.y;
}

// ---------------------------------------------------------------------------
// cp.async helpers
// ---------------------------------------------------------------------------
__device__ __forceinline__ uint32_t smem_u32(const void* p) {
    return (uint32_t)__cvta_generic_to_shared(p);
}
__device__ __forceinline__ void cp_async16(uint32_t dst, const void* src) {
    asm volatile("cp.async.ca.shared.global [%0], [%1], 16;" :: "r"(dst), "l"(src));
}
__device__ __forceinline__ void cp_async4(uint32_t dst, const void* src) {
    asm volatile("cp.async.ca.shared.global [%0], [%1], 4;" :: "r"(dst), "l"(src));
}
#define CP_COMMIT() asm volatile("cp.async.commit_group;")
#define CP_WAIT(N)  asm volatile("cp.async.wait_group %0;" :: "n"(N))

// ---------------------------------------------------------------------------
// Kernel 1: dtype-detect + group samples by task. 256 threads, shuffle scan.
// ---------------------------------------------------------------------------
__global__ void __launch_bounds__(256)
group_kernel(const void* __restrict__ task_ptr) {
    __shared__ int counts[TT];
    __shared__ int cursor[TT];
    __shared__ int odd_or;
    int tid = threadIdx.x;
    if (tid < TT) counts[tid] = 0;
    if (tid == 0) odd_or = 0;
    __syncthreads();

    // words 4t..4t+3 (first 4KB -- in-bounds for both dtypes)
    int4 v = ((const int4*)task_ptr)[tid];
    if ((v.y | v.w) != 0) atomicOr(&odd_or, 1);
    __syncthreads();
    bool is64 = (odd_or == 0);

    int tk[4];
    if (is64) {
        int4 a = ((const int4*)task_ptr)[2 * tid];
        int4 b = ((const int4*)task_ptr)[2 * tid + 1];
        tk[0] = a.x; tk[1] = a.z; tk[2] = b.x; tk[3] = b.z;
    } else {
        tk[0] = v.x; tk[1] = v.y; tk[2] = v.z; tk[3] = v.w;
    }
#pragma unroll
    for (int r = 0; r < 4; r++) {
        tk[r] &= (TT - 1);
        atomicAdd(&counts[tk[r]], 1);
    }
    __syncthreads();

    if (tid < 32) {
        int lane = tid;
        int c0 = counts[lane], c1 = counts[lane + 32];
        int s0 = c0, s1 = c1;
#pragma unroll
        for (int off = 1; off < 32; off <<= 1) {
            int n0 = __shfl_up_sync(0xFFFFFFFFu, s0, off);
            int n1 = __shfl_up_sync(0xFFFFFFFFu, s1, off);
            if (lane >= off) { s0 += n0; s1 += n1; }
        }
        int tot0  = __shfl_sync(0xFFFFFFFFu, s0, 31);
        int s1_31 = __shfl_sync(0xFFFFFFFFu, s1, 31);   // uniform: whole warp executes
        int e0 = s0 - c0;
        int e1 = tot0 + s1 - c1;
        cursor[lane] = e0;       cursor[lane + 32] = e1;
        g_start[lane] = e0;      g_start[lane + 32] = e1;
        if (lane == 31) g_start[TT] = tot0 + s1_31;
    }
    __syncthreads();
#pragma unroll
    for (int r = 0; r < 4; r++) {
        int pos = atomicAdd(&cursor[tk[r]], 1);
        g_sorted[pos] = 4 * tid + r;
    }
}

// ---------------------------------------------------------------------------
// Kernel 2: fc1 per-task GEMM  h = relu(x * W1[t] + b1[t])
// grid (H/128, T), 128 threads. Tile M=16, N=128, K-step 32.
// cp.async double-buffered; X staged coalesced into padded transpose [32][17].
// ---------------------------------------------------------------------------
__global__ void __launch_bounds__(128)
fc1_kernel(const float* __restrict__ xs, const float* __restrict__ w1,
           const float* __restrict__ b1) {
    int task = blockIdx.y;
    int n0 = blockIdx.x * 128;
    int start = g_start[task], end = g_start[task + 1];
    if (start == end) return;

    __shared__ float Xs[2][32][17];
    __shared__ float Ws[2][32][128];
    __shared__ float bias[128];

    int tid = threadIdx.x;
    int wrp = tid >> 5, lane = tid & 31;
    int tm = tid & 3;
    int tn = tid >> 2;
    const float* w1t = w1 + (size_t)task * DD * HH + n0;
    bias[tid] = b1[task * HH + n0 + tid];

    for (int m0 = start; m0 < end; m0 += 16) {
        // row pointers for this warp's 4 staging rows
        const float* rowp[4];
        bool rowok[4];
#pragma unroll
        for (int r = 0; r < 4; r++) {
            int gm = m0 + wrp * 4 + r;
            rowok[r] = (gm < end);
            rowp[r] = rowok[r] ? xs + (size_t)g_sorted[gm] * DD : xs;
        }
        if (m0 + 16 > end) {   // tail: zero X buffers once (OOB rows never written)
            for (int i = tid; i < 2 * 32 * 17; i += 128) ((float*)Xs)[i] = 0.f;
        }
        __syncthreads();

        float acc[4][4];
#pragma unroll
        for (int i = 0; i < 4; i++)
#pragma unroll
            for (int j = 0; j < 4; j++) acc[i][j] = 0.f;

        // ---- issue load for k-tile t into buffer b ----
        auto issue_load = [&](int t, int b) {
            int k0 = t * 32;
            // W: 8 x 16B per thread, coalesced rows
#pragma unroll
            for (int i = 0; i < 8; i++) {
                int idx = tid + i * 128;          // float4 index in tile
                int kk = idx >> 5;                 // 128 floats = 32 float4 per row
                int n4 = idx & 31;
                cp_async16(smem_u32(&Ws[b][kk][n4 * 4]),
                           w1t + (size_t)(k0 + kk) * HH + n4 * 4);
            }
            // X: 4 rows per warp, lane reads one float of row segment (coalesced)
#pragma unroll
            for (int r = 0; r < 4; r++) {
                if (rowok[r])
                    cp_async4(smem_u32(&Xs[b][lane][wrp * 4 + r]),
                              rowp[r] + k0 + lane);
            }
        };

        issue_load(0, 0);
        CP_COMMIT();

        for (int t = 0; t < 16; t++) {
            int buf = t & 1;
            if (t + 1 < 16) { issue_load(t + 1, buf ^ 1); CP_COMMIT(); CP_WAIT(1); }
            else            { CP_WAIT(0); }
            __syncthreads();
#pragma unroll
            for (int kk = 0; kk < 32; kk++) {
                float4 wv = *(const float4*)&Ws[buf][kk][tn * 4];
                float x0 = Xs[buf][kk][tm * 4 + 0];
                float x1 = Xs[buf][kk][tm * 4 + 1];
                float x2 = Xs[buf][kk][tm * 4 + 2];
                float x3 = Xs[buf][kk][tm * 4 + 3];
                acc[0][0] += x0 * wv.x; acc[0][1] += x0 * wv.y; acc[0][2] += x0 * wv.z; acc[0][3] += x0 * wv.w;
                acc[1][0] += x1 * wv.x; acc[1][1] += x1 * wv.y; acc[1][2] += x1 * wv.z; acc[1][3] += x1 * wv.w;
                acc[2][0] += x2 * wv.x; acc[2][1] += x2 * wv.y; acc[2][2] += x2 * wv.z; acc[2][3] += x2 * wv.w;
                acc[3][0] += x3 * wv.x; acc[3][1] += x3 * wv.y; acc[3][2] += x3 * wv.z; acc[3][3] += x3 * wv.w;
            }
            __syncthreads();
        }

        // epilogue: bias + relu, store sorted-order hidden rows
#pragma unroll
        for (int i = 0; i < 4; i++) {
            int gm = m0 + tm * 4 + i;
            if (gm < end) {
                float4 o;
                o.x = fmaxf(acc[i][0] + bias[tn * 4 + 0], 0.f);
                o.y = fmaxf(acc[i][1] + bias[tn * 4 + 1], 0.f);
                o.z = fmaxf(acc[i][2] + bias[tn * 4 + 2], 0.f);
                o.w = fmaxf(acc[i][3] + bias[tn * 4 + 3], 0.f);
                *(float4*)&g_h[(size_t)gm * HH + n0 + tn * 4] = o;
            }
        }
        __syncthreads();
    }
}

// ---------------------------------------------------------------------------
// Kernel 3: fc2 + log_softmax + categorical + log_prob + entropy
// grid (2, T), 256 threads (8 warps). Warp per sample; 2 blocks split samples.
// ---------------------------------------------------------------------------
__global__ void __launch_bounds__(256)
fc2_kernel(const float* __restrict__ w2, const float* __restrict__ b2,
           float* __restrict__ out, int out_mode) {
    int task = blockIdx.y;
    __shared__ float Ws[DD * 19];
    __shared__ float b2s[AA];
    int tid = threadIdx.x;

    const float* w2t = w2 + (size_t)task * DD * AA;
    for (int i = tid; i < DD * AA; i += 256) {
        int k = i / AA, a = i % AA;
        Ws[k * 19 + a] = w2t[i];
    }
    if (tid < AA) b2s[tid] = b2[task * AA + tid];
    __syncthreads();

    int start = g_start[task], end = g_start[task + 1];
    int warp = tid >> 5, lane = tid & 31;

    for (int m = start + blockIdx.x * 8 + warp; m < end; m += 16) {
        const float* hrow = g_h + (size_t)m * HH;
        float acc[AA];
#pragma unroll
        for (int a = 0; a < AA; a++) acc[a] = 0.f;

        for (int k = lane; k < HH; k += 32) {
            float hv = hrow[k];
            const float* wr = &Ws[k * 19];
#pragma unroll
            for (int a = 0; a < AA; a++) acc[a] += hv * wr[a];
        }
#pragma unroll
        for (int off = 16; off; off >>= 1)
#pragma unroll
            for (int a = 0; a < AA; a++)
                acc[a] += __shfl_xor_sync(0xFFFFFFFFu, acc[a], off);

        int b = g_sorted[m];
        float logit = (lane < AA) ? acc[lane] + b2s[lane] : -INFINITY;

        float mx = logit;
#pragma unroll
        for (int off = 16; off; off >>= 1)
            mx = fmaxf(mx, __shfl_xor_sync(0xFFFFFFFFu, mx, off));
        float ex = (lane < AA) ? expf(logit - mx) : 0.f;
        float s = ex;
#pragma unroll
        for (int off = 16; off; off >>= 1)
            s += __shfl_xor_sync(0xFFFFFFFFu, s, off);
        float lse = logf(s);
        float logp = logit - mx - lse;

        float v = -INFINITY;
        if (lane < AA) {
            uint32_t bits = jax_bits(b * AA + lane);
            float f = __uint_as_float((bits >> 9) | 0x3f800000u) - 1.0f;
            const float tiny = 1.1754943508222875e-38f;
            float u = fmaxf(tiny, f + tiny);
            float g = -logf(-logf(u));
            v = logit + g;
        }
        float bv = v;
        int bi = (lane < AA) ? lane : 31;
#pragma unroll
        for (int off = 16; off; off >>= 1) {
            float ov = __shfl_xor_sync(0xFFFFFFFFu, bv, off);
            int oi = __shfl_xor_sync(0xFFFFFFFFu, bi, off);
            if (ov > bv || (ov == bv && oi < bi)) { bv = ov; bi = oi; }
        }
        int action = bi;
        float lp_sel = __shfl_sync(0xFFFFFFFFu, logp, action);

        float term = (lane < AA) ? -(ex / s) * logp : 0.f;
        float ent = term;
#pragma unroll
        for (int off = 16; off; off >>= 1)
            ent += __shfl_xor_sync(0xFFFFFFFFu, ent, off);

        if (lane == 0) {
            if (out_mode == 0) {
                out[b]          = (float)action;
                out[BB + b]     = lp_sel;
                out[2 * BB + b] = ent;
            } else {
                ((long long*)out)[b] = (long long)action;
                out[2 * BB + b]      = lp_sel;
                out[3 * BB + b]      = ent;
            }
        }
    }
}

// ---------------------------------------------------------------------------
extern "C" void kernel_launch(void* const* d_in, const int* in_sizes, int n_in,
                              void* d_out, int out_size) {
    const float* xs = nullptr; const void* task_id = nullptr;
    const float* w1 = nullptr; const float* b1 = nullptr;
    const float* w2 = nullptr; const float* b2 = nullptr;
    for (int i = 0; i < n_in; i++) {
        switch (in_sizes[i]) {
            case BB * DD:       xs      = (const float*)d_in[i]; break;
            case BB:            task_id = d_in[i];               break;
            case TT * DD * HH:  w1      = (const float*)d_in[i]; break;
            case TT * HH:       b1      = (const float*)d_in[i]; break;
            case TT * HH * AA:  w2      = (const float*)d_in[i]; break;
            case TT * AA:       b2      = (const float*)d_in[i]; break;
            default: break;
        }
    }
    float* out = (float*)d_out;
    int out_mode = (out_size == 4 * BB) ? 1 : 0;

    group_kernel<<<1, 256>>>(task_id);
    dim3 g1(HH / 128, TT);
    fc1_kernel<<<g1, 128>>>(xs, w1, b1);
    dim3 g2(2, TT);
    fc2_kernel<<<g2, 256>>>(w2, b2, out, out_mode);
}